// round 8
// baseline (speedup 1.0000x reference)
#include <cuda_runtime.h>
#include <cuda_fp16.h>

typedef unsigned long long u64;
typedef unsigned int u32;

#define WB 8
#define NW 16
#define CTA_THREADS 512
#define TPTS 10
#define DDIM 32
#define NEXP 8

// ---- shared memory layout (float-slot offsets) ----
// two expert weight buffers (ring), each 8416 floats
#define EXPBUF 8416
#define SGW1  16832      // 4096
#define SGB1  20928      // 64
#define SGW2  20992      // 512
#define SGB2  21504      // 8
#define SACT  21512
// per-warp activation region (fp16 acts): inp 132 | hbuf 256 | f(half) 1024
#define OFF_H   132
#define OFF_F   388
#define WARP_ACT 1412
#define SMEM_BYTES ((SACT + NW * WARP_ACT) * 4)   // 176416 bytes, 1 CTA/SM

// offsets inside an expert buffer
#define OW1 0
#define OB1 2112
#define OW2 2176
#define OB2 6272
#define OW3 6336
#define OB3 8384

static __device__ __forceinline__ u64 pack2(float lo, float hi){
    u64 r; asm("mov.b64 %0,{%1,%2};" : "=l"(r) : "f"(lo), "f"(hi)); return r;
}
static __device__ __forceinline__ void unpack2(u64 v, float &lo, float &hi){
    asm("mov.b64 {%0,%1},%2;" : "=f"(lo), "=f"(hi) : "l"(v));
}
static __device__ __forceinline__ u64 ffma2(u64 a, u64 b, u64 c){
    u64 d; asm("fma.rn.f32x2 %0,%1,%2,%3;" : "=l"(d) : "l"(a), "l"(b), "l"(c)); return d;
}
// half2 (lo,hi) -> f32x2 u64
static __device__ __forceinline__ u64 h2_to_f2(u32 h){
    float lo, hi;
    asm("{.reg .f16 l,h; mov.b32 {l,h}, %2; cvt.f32.f16 %0, l; cvt.f32.f16 %1, h;}"
        : "=f"(lo), "=f"(hi) : "r"(h));
    return pack2(lo, hi);
}
// (lo,hi) floats -> half2 u32 (single F2FP)
static __device__ __forceinline__ u32 f2_to_h2(float lo, float hi){
    u32 r; asm("cvt.rn.f16x2.f32 %0, %2, %1;" : "=r"(r) : "f"(lo), "f"(hi)); return r;
}
static __device__ __forceinline__ float tanh_fast(float x){
    float e, r;
    asm("ex2.approx.f32 %0,%1;" : "=f"(e) : "f"(x * 2.8853900817779268f));
    asm("rcp.approx.f32 %0,%1;" : "=f"(r) : "f"(e + 1.0f));
    return fmaf(-2.0f, r, 1.0f);
}
static __device__ __forceinline__ float exp_fast(float x){
    float e; asm("ex2.approx.f32 %0,%1;" : "=f"(e) : "f"(x * 1.4426950408889634f)); return e;
}
static __device__ __forceinline__ float rcp_fast(float x){
    float r; asm("rcp.approx.f32 %0,%1;" : "=f"(r) : "f"(x)); return r;
}

static __device__ __forceinline__ void cp16(u32 dst_smem, const float4* src){
    asm volatile("cp.async.cg.shared.global [%0],[%1],16;" :: "r"(dst_smem), "l"(src));
}
static __device__ __forceinline__ void copy_async(float* dst, const float* __restrict__ src,
                                                  int n4, int tid){
    u32 d = (u32)__cvta_generic_to_shared(dst);
    const float4* s = (const float4*)src;
    for (int i = tid; i < n4; i += CTA_THREADS) cp16(d + i * 16, s + i);
}
static __device__ __forceinline__ void copy_f4(float* dst, const float* __restrict__ src,
                                               int n4, int tid){
    const float4* s = (const float4*)src;
    float4* d = (float4*)dst;
    for (int i = tid; i < n4; i += CTA_THREADS) d[i] = s[i];
}

// row-MAC, fp16 activation row (uint4 = 4 half2 = 8 batch), 2 weight cols
#define ROWMAC8H(acc, rowptr_u32, w0p, w1p) { \
    uint4 ah_ = *(const uint4*)(rowptr_u32); \
    u64 p0_ = h2_to_f2(ah_.x), p1_ = h2_to_f2(ah_.y); \
    u64 p2_ = h2_to_f2(ah_.z), p3_ = h2_to_f2(ah_.w); \
    acc[0] = ffma2(w0p, p0_, acc[0]); acc[1] = ffma2(w0p, p1_, acc[1]); \
    acc[2] = ffma2(w0p, p2_, acc[2]); acc[3] = ffma2(w0p, p3_, acc[3]); \
    acc[4] = ffma2(w1p, p0_, acc[4]); acc[5] = ffma2(w1p, p1_, acc[5]); \
    acc[6] = ffma2(w1p, p2_, acc[6]); acc[7] = ffma2(w1p, p3_, acc[7]); }

struct WPtrs { const float *gW1, *gb1, *gW2, *gb2, *gW3, *gb3; };

static __device__ __forceinline__ void stage_expert(float* buf, const WPtrs& g, int e, int tid){
    copy_async(buf + OW1, g.gW1 + e * 2112, 528, tid);
    copy_async(buf + OB1, g.gb1 + e * 64,    16, tid);
    copy_async(buf + OW2, g.gW2 + e * 4096, 1024, tid);
    copy_async(buf + OB2, g.gb2 + e * 64,    16, tid);
    copy_async(buf + OW3, g.gW3 + e * 2048,  512, tid);
    copy_async(buf + OB3, g.gb3 + e * 32,     8, tid);
    asm volatile("cp.async.commit_group;");
}

__global__ void __launch_bounds__(CTA_THREADS, 1)
ameode_kernel(const float* __restrict__ x0,  const float* __restrict__ tspan,
              const float* __restrict__ gW1, const float* __restrict__ gb1,
              const float* __restrict__ gW2, const float* __restrict__ gb2,
              const float* __restrict__ gW3, const float* __restrict__ gb3,
              const float* __restrict__ gGw1, const float* __restrict__ gGb1,
              const float* __restrict__ gGw2, const float* __restrict__ gGb2,
              float* __restrict__ out)
{
    extern __shared__ float sm[];
    const int tid  = threadIdx.x;
    const int lane = tid & 31;
    const int warp = tid >> 5;
    const int bbase = blockIdx.x * (NW * WB) + warp * WB;

    WPtrs g; g.gW1 = gW1; g.gb1 = gb1; g.gW2 = gW2; g.gb2 = gb2; g.gW3 = gW3; g.gb3 = gb3;

    copy_f4(sm + SGW1, gGw1, 1024, tid);
    copy_f4(sm + SGB1, gGb1,   16, tid);
    copy_f4(sm + SGW2, gGw2,  128, tid);
    copy_f4(sm + SGB2, gGb2,    2, tid);
    stage_expert(sm, g, 0, tid);   // prime ring

    u32*    sInpH = (u32*)(sm + SACT + warp * WARP_ACT);  // [33] rows x 4 half2
    u32*    sHBH  = sInpH + OFF_H * 1;                    // [64] rows x 4 half2 (u32 view)
    float*  sWGT  = (float*)sHBH;                         // wgt[8][8] fp32 (after gate-h dead)
    __half* sFh   = (__half*)(sInpH + OFF_F);             // [8][32][8] halfs

    float x[WB], xin[WB], ksum[WB];
    #pragma unroll
    for (int wb = 0; wb < WB; wb++){
        x[wb] = x0[(bbase + wb) * DDIM + lane];
        out[(bbase + wb) * (TPTS * DDIM) + lane] = x[wb];   // t = 0 row
    }

    #pragma unroll 1
    for (int s = 0; s < TPTS - 1; s++){
        const float t0 = tspan[s], t1 = tspan[s + 1];
        const float dt = t1 - t0;
        #pragma unroll
        for (int wb = 0; wb < WB; wb++){ xin[wb] = x[wb]; ksum[wb] = 0.f; }

        #pragma unroll 1
        for (int sub = 0; sub < 4; sub++){
            const float cc   = (sub == 0) ? 0.f : ((sub == 3) ? 1.f : 0.5f);
            const float tcur = fmaf(cc, dt, t0);

            // =================== dyn(tcur, xin) -> k ===================
            __syncwarp();
            {
                uint4 xi;
                xi.x = f2_to_h2(xin[0], xin[1]); xi.y = f2_to_h2(xin[2], xin[3]);
                xi.z = f2_to_h2(xin[4], xin[5]); xi.w = f2_to_h2(xin[6], xin[7]);
                *(uint4*)(sInpH + lane * 4) = xi;
                if (lane == 0){
                    u32 th = f2_to_h2(tcur, tcur);
                    uint4 tv; tv.x = th; tv.y = th; tv.z = th; tv.w = th;
                    *(uint4*)(sInpH + 32 * 4) = tv;
                }
            }
            __syncwarp();

            float dx[WB];
            #pragma unroll
            for (int wb = 0; wb < WB; wb++) dx[wb] = 0.f;

            #pragma unroll 1
            for (int e = 0; e < NEXP; e++){
                asm volatile("cp.async.wait_group 0;");
                __syncthreads();   // RAW for e; WAR for e-1's buffer
                stage_expert(sm + (((e + 1) & 1) * EXPBUF), g, (e + 1) & 7, tid);
                const float* W = sm + ((e & 1) * EXPBUF);

                // ---- L1: h = tanh(inp @ W1e + b1e); lane owns cols lane, lane+32
                {
                    u64 acc[8];
                    #pragma unroll
                    for (int p = 0; p < 8; p++) acc[p] = 0ull;
                    #pragma unroll 8
                    for (int i = 0; i < 32; i++){
                        float w0 = W[OW1 + i * 64 + lane];
                        float w1 = W[OW1 + i * 64 + 32 + lane];
                        u64 w0p = pack2(w0, w0), w1p = pack2(w1, w1);
                        ROWMAC8H(acc, sInpH + i * 4, w0p, w1p);
                    }
                    {
                        float w0 = W[OW1 + 32 * 64 + lane];
                        float w1 = W[OW1 + 32 * 64 + 32 + lane];
                        u64 w0p = pack2(w0, w0), w1p = pack2(w1, w1);
                        ROWMAC8H(acc, sInpH + 32 * 4, w0p, w1p);
                    }
                    float bl = W[OB1 + lane], bh = W[OB1 + 32 + lane];
                    uint4 r0, r1;
                    {
                        float lo, hi, a, b;
                        unpack2(acc[0], lo, hi); a = tanh_fast(lo + bl); b = tanh_fast(hi + bl); r0.x = f2_to_h2(a, b);
                        unpack2(acc[1], lo, hi); a = tanh_fast(lo + bl); b = tanh_fast(hi + bl); r0.y = f2_to_h2(a, b);
                        unpack2(acc[2], lo, hi); a = tanh_fast(lo + bl); b = tanh_fast(hi + bl); r0.z = f2_to_h2(a, b);
                        unpack2(acc[3], lo, hi); a = tanh_fast(lo + bl); b = tanh_fast(hi + bl); r0.w = f2_to_h2(a, b);
                        unpack2(acc[4], lo, hi); a = tanh_fast(lo + bh); b = tanh_fast(hi + bh); r1.x = f2_to_h2(a, b);
                        unpack2(acc[5], lo, hi); a = tanh_fast(lo + bh); b = tanh_fast(hi + bh); r1.y = f2_to_h2(a, b);
                        unpack2(acc[6], lo, hi); a = tanh_fast(lo + bh); b = tanh_fast(hi + bh); r1.z = f2_to_h2(a, b);
                        unpack2(acc[7], lo, hi); a = tanh_fast(lo + bh); b = tanh_fast(hi + bh); r1.w = f2_to_h2(a, b);
                    }
                    __syncwarp();
                    *(uint4*)(sHBH + lane * 4)        = r0;
                    *(uint4*)(sHBH + (lane + 32) * 4) = r1;
                    __syncwarp();
                }

                // ---- L2: h = tanh(h @ W2e + b2e)
                {
                    u64 acc[8];
                    #pragma unroll
                    for (int p = 0; p < 8; p++) acc[p] = 0ull;
                    #pragma unroll 8
                    for (int i = 0; i < 64; i++){
                        float w0 = W[OW2 + i * 64 + lane];
                        float w1 = W[OW2 + i * 64 + 32 + lane];
                        u64 w0p = pack2(w0, w0), w1p = pack2(w1, w1);
                        ROWMAC8H(acc, sHBH + i * 4, w0p, w1p);
                    }
                    float bl = W[OB2 + lane], bh = W[OB2 + 32 + lane];
                    uint4 r0, r1;
                    {
                        float lo, hi, a, b;
                        unpack2(acc[0], lo, hi); a = tanh_fast(lo + bl); b = tanh_fast(hi + bl); r0.x = f2_to_h2(a, b);
                        unpack2(acc[1], lo, hi); a = tanh_fast(lo + bl); b = tanh_fast(hi + bl); r0.y = f2_to_h2(a, b);
                        unpack2(acc[2], lo, hi); a = tanh_fast(lo + bl); b = tanh_fast(hi + bl); r0.z = f2_to_h2(a, b);
                        unpack2(acc[3], lo, hi); a = tanh_fast(lo + bl); b = tanh_fast(hi + bl); r0.w = f2_to_h2(a, b);
                        unpack2(acc[4], lo, hi); a = tanh_fast(lo + bh); b = tanh_fast(hi + bh); r1.x = f2_to_h2(a, b);
                        unpack2(acc[5], lo, hi); a = tanh_fast(lo + bh); b = tanh_fast(hi + bh); r1.y = f2_to_h2(a, b);
                        unpack2(acc[6], lo, hi); a = tanh_fast(lo + bh); b = tanh_fast(hi + bh); r1.z = f2_to_h2(a, b);
                        unpack2(acc[7], lo, hi); a = tanh_fast(lo + bh); b = tanh_fast(hi + bh); r1.w = f2_to_h2(a, b);
                    }
                    __syncwarp();   // all lanes done reading h1
                    *(uint4*)(sHBH + lane * 4)        = r0;
                    *(uint4*)(sHBH + (lane + 32) * 4) = r1;
                    __syncwarp();
                }

                // ---- L3: f = h @ W3e + b3e ; lane owns col d = lane; store fp16
                {
                    u64 a3[4];
                    #pragma unroll
                    for (int p = 0; p < 4; p++) a3[p] = 0ull;
                    #pragma unroll 8
                    for (int kk = 0; kk < 64; kk++){
                        float w = W[OW3 + kk * 32 + lane];
                        u64 wp = pack2(w, w);
                        uint4 ah = *(const uint4*)(sHBH + kk * 4);
                        a3[0] = ffma2(wp, h2_to_f2(ah.x), a3[0]);
                        a3[1] = ffma2(wp, h2_to_f2(ah.y), a3[1]);
                        a3[2] = ffma2(wp, h2_to_f2(ah.z), a3[2]);
                        a3[3] = ffma2(wp, h2_to_f2(ah.w), a3[3]);
                    }
                    float b3v = W[OB3 + lane];
                    float fv[8];
                    #pragma unroll
                    for (int p = 0; p < 4; p++){
                        float lo, hi; unpack2(a3[p], lo, hi);
                        fv[2*p] = lo + b3v; fv[2*p+1] = hi + b3v;
                    }
                    uint4 pk;
                    pk.x = f2_to_h2(fv[0], fv[1]); pk.y = f2_to_h2(fv[2], fv[3]);
                    pk.z = f2_to_h2(fv[4], fv[5]); pk.w = f2_to_h2(fv[6], fv[7]);
                    ((uint4*)sFh)[e * 32 + lane] = pk;
                    #pragma unroll
                    for (int wb = 0; wb < WB; wb++) dx[wb] += fv[wb];
                }
            } // expert loop  (next eval's expert-0 prefetch overlaps gating)

            // ---- gating: gin = concat(xin, mean_e f) in hbuf (fp16) ----
            {
                uint4 gi0, gi1;
                gi0.x = f2_to_h2(xin[0], xin[1]); gi0.y = f2_to_h2(xin[2], xin[3]);
                gi0.z = f2_to_h2(xin[4], xin[5]); gi0.w = f2_to_h2(xin[6], xin[7]);
                gi1.x = f2_to_h2(dx[0]*0.125f, dx[1]*0.125f); gi1.y = f2_to_h2(dx[2]*0.125f, dx[3]*0.125f);
                gi1.z = f2_to_h2(dx[4]*0.125f, dx[5]*0.125f); gi1.w = f2_to_h2(dx[6]*0.125f, dx[7]*0.125f);
                *(uint4*)(sHBH + lane * 4)        = gi0;
                *(uint4*)(sHBH + (lane + 32) * 4) = gi1;
            }
            __syncwarp();
            {
                u64 ag[8];
                #pragma unroll
                for (int p = 0; p < 8; p++) ag[p] = 0ull;
                #pragma unroll 8
                for (int i = 0; i < 64; i++){
                    float w0 = sm[SGW1 + i * 64 + lane];
                    float w1 = sm[SGW1 + i * 64 + 32 + lane];
                    u64 w0p = pack2(w0, w0), w1p = pack2(w1, w1);
                    ROWMAC8H(ag, sHBH + i * 4, w0p, w1p);
                }
                float bl = sm[SGB1 + lane], bh = sm[SGB1 + 32 + lane];
                uint4 r0, r1;
                {
                    float lo, hi, a, b;
                    unpack2(ag[0], lo, hi); a = tanh_fast(lo + bl); b = tanh_fast(hi + bl); r0.x = f2_to_h2(a, b);
                    unpack2(ag[1], lo, hi); a = tanh_fast(lo + bl); b = tanh_fast(hi + bl); r0.y = f2_to_h2(a, b);
                    unpack2(ag[2], lo, hi); a = tanh_fast(lo + bl); b = tanh_fast(hi + bl); r0.z = f2_to_h2(a, b);
                    unpack2(ag[3], lo, hi); a = tanh_fast(lo + bl); b = tanh_fast(hi + bl); r0.w = f2_to_h2(a, b);
                    unpack2(ag[4], lo, hi); a = tanh_fast(lo + bh); b = tanh_fast(hi + bh); r1.x = f2_to_h2(a, b);
                    unpack2(ag[5], lo, hi); a = tanh_fast(lo + bh); b = tanh_fast(hi + bh); r1.y = f2_to_h2(a, b);
                    unpack2(ag[6], lo, hi); a = tanh_fast(lo + bh); b = tanh_fast(hi + bh); r1.z = f2_to_h2(a, b);
                    unpack2(ag[7], lo, hi); a = tanh_fast(lo + bh); b = tanh_fast(hi + bh); r1.w = f2_to_h2(a, b);
                }
                __syncwarp();   // gin consumed
                *(uint4*)(sHBH + lane * 4)        = r0;
                *(uint4*)(sHBH + (lane + 32) * 4) = r1;
                __syncwarp();
            }
            // ---- logits + softmax: lane = expert ep x quarter q of H
            float wgt[WB];
            {
                const int ep = lane & 7, q = lane >> 3;
                u64 z2[4];
                #pragma unroll
                for (int p = 0; p < 4; p++) z2[p] = 0ull;
                #pragma unroll 4
                for (int r = 0; r < 16; r++){
                    int j = q * 16 + r;
                    float w = sm[SGW2 + j * 8 + ep];
                    u64 wp = pack2(w, w);
                    uint4 ah = *(const uint4*)(sHBH + j * 4);
                    z2[0] = ffma2(wp, h2_to_f2(ah.x), z2[0]);
                    z2[1] = ffma2(wp, h2_to_f2(ah.y), z2[1]);
                    z2[2] = ffma2(wp, h2_to_f2(ah.z), z2[2]);
                    z2[3] = ffma2(wp, h2_to_f2(ah.w), z2[3]);
                }
                float z[WB];
                #pragma unroll
                for (int p = 0; p < 4; p++){ unpack2(z2[p], z[2*p], z[2*p+1]); }
                float gb2v = sm[SGB2 + ep];
                #pragma unroll
                for (int v = 0; v < WB; v++){
                    z[v] += __shfl_xor_sync(0xffffffffu, z[v], 8);
                    z[v] += __shfl_xor_sync(0xffffffffu, z[v], 16);
                    z[v] += gb2v;
                    float m = z[v];
                    m = fmaxf(m, __shfl_xor_sync(0xffffffffu, m, 1));
                    m = fmaxf(m, __shfl_xor_sync(0xffffffffu, m, 2));
                    m = fmaxf(m, __shfl_xor_sync(0xffffffffu, m, 4));
                    float p = exp_fast(z[v] - m);
                    float ss = p;
                    ss += __shfl_xor_sync(0xffffffffu, ss, 1);
                    ss += __shfl_xor_sync(0xffffffffu, ss, 2);
                    ss += __shfl_xor_sync(0xffffffffu, ss, 4);
                    wgt[v] = p * rcp_fast(ss);
                }
            }
            __syncwarp();   // gate-h consumed
            if (lane < 8){  // q==0 lanes publish wgt[e=lane][wb] as fp32
                *(float4*)(sWGT + lane * 8)     = make_float4(wgt[0], wgt[1], wgt[2], wgt[3]);
                *(float4*)(sWGT + lane * 8 + 4) = make_float4(wgt[4], wgt[5], wgt[6], wgt[7]);
            }
            __syncwarp();

            // ---- k = sum_e wgt[e] * f[e] (f in fp16)
            float k[WB];
            #pragma unroll
            for (int wb = 0; wb < WB; wb++) k[wb] = 0.f;
            #pragma unroll
            for (int e2 = 0; e2 < NEXP; e2++){
                float4 wa = *(const float4*)(sWGT + e2 * 8);
                float4 wv = *(const float4*)(sWGT + e2 * 8 + 4);
                uint4 pk = ((const uint4*)sFh)[e2 * 32 + lane];
                float2 f01 = __half22float2(*(__half2*)&pk.x);
                float2 f23 = __half22float2(*(__half2*)&pk.y);
                float2 f45 = __half22float2(*(__half2*)&pk.z);
                float2 f67 = __half22float2(*(__half2*)&pk.w);
                k[0] = fmaf(wa.x, f01.x, k[0]); k[1] = fmaf(wa.y, f01.y, k[1]);
                k[2] = fmaf(wa.z, f23.x, k[2]); k[3] = fmaf(wa.w, f23.y, k[3]);
                k[4] = fmaf(wv.x, f45.x, k[4]); k[5] = fmaf(wv.y, f45.y, k[5]);
                k[6] = fmaf(wv.z, f67.x, k[6]); k[7] = fmaf(wv.w, f67.y, k[7]);
            }
            // =================== end dyn ===================

            const float wsum = (sub == 0 || sub == 3) ? 1.f : 2.f;
            #pragma unroll
            for (int wb = 0; wb < WB; wb++) ksum[wb] = fmaf(wsum, k[wb], ksum[wb]);
            if (sub < 3){
                const float nc = (sub == 2) ? dt : 0.5f * dt;
                #pragma unroll
                for (int wb = 0; wb < WB; wb++) xin[wb] = fmaf(nc, k[wb], x[wb]);
            }
        } // sub

        const float sc = dt * (1.0f / 6.0f);
        #pragma unroll
        for (int wb = 0; wb < WB; wb++){
            x[wb] = fmaf(sc, ksum[wb], x[wb]);
            out[(bbase + wb) * (TPTS * DDIM) + (s + 1) * DDIM + lane] = x[wb];
        }
    } // step
}

extern "C" void kernel_launch(void* const* d_in, const int* in_sizes, int n_in,
                              void* d_out, int out_size)
{
    (void)in_sizes; (void)n_in; (void)out_size;
    cudaFuncSetAttribute(ameode_kernel, cudaFuncAttributeMaxDynamicSharedMemorySize, SMEM_BYTES);
    ameode_kernel<<<128, CTA_THREADS, SMEM_BYTES>>>(
        (const float*)d_in[0],  (const float*)d_in[1],
        (const float*)d_in[2],  (const float*)d_in[3],
        (const float*)d_in[4],  (const float*)d_in[5],
        (const float*)d_in[6],  (const float*)d_in[7],
        (const float*)d_in[8],  (const float*)d_in[9],
        (const float*)d_in[10], (const float*)d_in[11],
        (float*)d_out);
}

// round 11
// speedup vs baseline: 5.8572x; 5.8572x over previous
#include <cuda_runtime.h>
#include <cuda_fp16.h>

typedef unsigned int u32;

#define TPTS 10
#define CTA 256

// ---- smem byte offsets ----
#define EXPW   19200
#define SW1F   0
#define SW2F   6144
#define SW3F   14336
#define SB1    18432
#define SB2    18688
#define SB3    18944
#define SGW1F  38400
#define SGW2F  46592
#define SGB1   47616
#define SGB2   47872
#define SFBASE 48128      // F[warp][e][lane][32B]
#define SWGTO  113664     // wgt[warp][16][8] f32
#define SMEM_BYTES 117760

// weights pre-arranged in B-fragment register order
__device__ __align__(16) u32 g_W1F[8*3*8*64];
__device__ __align__(16) u32 g_W2F[8*4*8*64];
__device__ __align__(16) u32 g_W3F[8*4*4*64];
__device__ __align__(16) u32 g_GW1F[4*8*64];
__device__ __align__(16) u32 g_GW2F[4*64];

static __device__ __forceinline__ u32 f2h2(float lo, float hi){
    u32 r; asm("cvt.rn.f16x2.f32 %0, %2, %1;" : "=r"(r) : "f"(lo), "f"(hi)); return r;
}
static __device__ __forceinline__ float2 h22f2(u32 h){
    __half2 v = *(__half2*)&h; return __half22float2(v);
}
static __device__ __forceinline__ float tanh_fast(float x){
    float e, r;
    asm("ex2.approx.f32 %0,%1;" : "=f"(e) : "f"(x * 2.8853900817779268f));
    asm("rcp.approx.f32 %0,%1;" : "=f"(r) : "f"(e + 1.0f));
    return fmaf(-2.0f, r, 1.0f);
}
static __device__ __forceinline__ float exp_fast(float x){
    float e; asm("ex2.approx.f32 %0,%1;" : "=f"(e) : "f"(x * 1.4426950408889634f)); return e;
}
static __device__ __forceinline__ float rcp_fast(float x){
    float r; asm("rcp.approx.f32 %0,%1;" : "=f"(r) : "f"(x)); return r;
}

#define MMA4(d, a0,a1,a2,a3, b) \
    asm volatile("mma.sync.aligned.m16n8k16.row.col.f32.f16.f16.f32 " \
        "{%0,%1,%2,%3},{%4,%5,%6,%7},{%8,%9},{%0,%1,%2,%3};" \
        : "+f"((d)[0]),"+f"((d)[1]),"+f"((d)[2]),"+f"((d)[3]) \
        : "r"(a0),"r"(a1),"r"(a2),"r"(a3),"r"((b).x),"r"((b).y))

static __device__ __forceinline__ void stage16(u32 dst, const char* src, int n16, int tid){
    for (int i = tid; i < n16; i += CTA)
        asm volatile("cp.async.cg.shared.global [%0],[%1],16;"
                     :: "r"(dst + (u32)i*16), "l"(src + i*16));
}
static __device__ __forceinline__ void stage_expert(u32 sbuf, int e, int tid,
                                                    const float* b1, const float* b2, const float* b3){
    stage16(sbuf + SW1F, (const char*)g_W1F + e*6144, 384, tid);
    stage16(sbuf + SW2F, (const char*)g_W2F + e*8192, 512, tid);
    stage16(sbuf + SW3F, (const char*)g_W3F + e*4096, 256, tid);
    stage16(sbuf + SB1, (const char*)(b1 + e*64), 16, tid);
    stage16(sbuf + SB2, (const char*)(b2 + e*64), 16, tid);
    stage16(sbuf + SB3, (const char*)(b3 + e*32),  8, tid);
    asm volatile("cp.async.commit_group;" ::: "memory");
}

// epilogue for N=64 layers: acc(+bias) -> tanh -> A-fragments
#define EPI64(acc, biasptr, HA) { \
    const float* _b = (const float*)(biasptr); \
    _Pragma("unroll") \
    for (int j = 0; j < 8; j++){ \
        float2 bv = *(const float2*)(_b + j*8 + 2*q); \
        float c0 = tanh_fast((acc)[j*4+0] + bv.x); \
        float c1 = tanh_fast((acc)[j*4+1] + bv.y); \
        float c2 = tanh_fast((acc)[j*4+2] + bv.x); \
        float c3 = tanh_fast((acc)[j*4+3] + bv.y); \
        (HA)[(j>>1)*4 + (j&1)*2 + 0] = f2h2(c0, c1); \
        (HA)[(j>>1)*4 + (j&1)*2 + 1] = f2h2(c2, c3); \
    } }

// ---------------- weight frag-order pre-kernel ----------------
__global__ void conv_weights(const float* __restrict__ W1, const float* __restrict__ W2,
                             const float* __restrict__ W3, const float* __restrict__ Gw1,
                             const float* __restrict__ Gw2){
    int i0 = blockIdx.x*blockDim.x + threadIdx.x, st = gridDim.x*blockDim.x;
    for (int i = i0; i < 8*3*8*64; i += st){
        int r = i & 1, t = i >> 1, l = t & 31; t >>= 5;
        int j = t & 7; t >>= 3; int ks = t % 3, e = t / 3;
        int k = ks*16 + (l&3)*2 + r*8, n = j*8 + (l>>2);
        float lo = (k   < 33) ? W1[e*2112 + k*64 + n]     : 0.f;
        float hi = (k+1 < 33) ? W1[e*2112 + (k+1)*64 + n] : 0.f;
        __half2 h = __floats2half2_rn(lo, hi);
        g_W1F[i] = *(u32*)&h;
    }
    for (int i = i0; i < 8*4*8*64; i += st){
        int r = i & 1, t = i >> 1, l = t & 31; t >>= 5;
        int j = t & 7; t >>= 3; int ks = t & 3, e = t >> 2;
        int k = ks*16 + (l&3)*2 + r*8, n = j*8 + (l>>2);
        __half2 h = __floats2half2_rn(W2[e*4096 + k*64 + n], W2[e*4096 + (k+1)*64 + n]);
        g_W2F[i] = *(u32*)&h;
    }
    for (int i = i0; i < 8*4*4*64; i += st){
        int r = i & 1, t = i >> 1, l = t & 31; t >>= 5;
        int j = t & 3; t >>= 2; int ks = t & 3, e = t >> 2;
        int k = ks*16 + (l&3)*2 + r*8, n = j*8 + (l>>2);
        __half2 h = __floats2half2_rn(W3[e*2048 + k*32 + n], W3[e*2048 + (k+1)*32 + n]);
        g_W3F[i] = *(u32*)&h;
    }
    for (int i = i0; i < 4*8*64; i += st){
        int r = i & 1, t = i >> 1, l = t & 31; t >>= 5;
        int j = t & 7, ks = t >> 3;
        int k = ks*16 + (l&3)*2 + r*8, n = j*8 + (l>>2);
        __half2 h = __floats2half2_rn(Gw1[k*64 + n], Gw1[(k+1)*64 + n]);
        g_GW1F[i] = *(u32*)&h;
    }
    for (int i = i0; i < 4*64; i += st){
        int r = i & 1, t = i >> 1, l = t & 31; t >>= 5;
        int ks = t;
        int k = ks*16 + (l&3)*2 + r*8, n = l >> 2;
        __half2 h = __floats2half2_rn(Gw2[k*8 + n], Gw2[(k+1)*8 + n]);
        g_GW2F[i] = *(u32*)&h;
    }
}

// ---------------- main kernel ----------------
__global__ void __launch_bounds__(CTA, 1)
ameode_mma(const float* __restrict__ x0, const float* __restrict__ tspan,
           const float* __restrict__ b1, const float* __restrict__ b2, const float* __restrict__ b3,
           const float* __restrict__ Gb1, const float* __restrict__ Gb2,
           float* __restrict__ out)
{
    extern __shared__ char smem[];
    u32 sb = (u32)__cvta_generic_to_shared(smem);
    const int tid = threadIdx.x, lane = tid & 31, warp = tid >> 5;
    const int g = lane >> 2, q = lane & 3;
    const int row0 = blockIdx.x*128 + warp*16 + g;    // rows row0, row0+8

    // stage gate weights + expert 0 (single commit group)
    stage16(sb + SGW1F, (const char*)g_GW1F, 512, tid);
    stage16(sb + SGW2F, (const char*)g_GW2F, 64, tid);
    stage16(sb + SGB1, (const char*)Gb1, 16, tid);
    stage16(sb + SGB2, (const char*)Gb2, 2, tid);
    stage_expert(sb, 0, tid, b1, b2, b3);

    float x[16], ksum[16], kk[16];
    #pragma unroll
    for (int c = 0; c < 16; c++) kk[c] = 0.f;
    #pragma unroll
    for (int j = 0; j < 4; j++){
        float2 a = *(const float2*)(x0 + row0*32 + j*8 + 2*q);
        float2 b = *(const float2*)(x0 + (row0+8)*32 + j*8 + 2*q);
        x[j*4+0] = a.x; x[j*4+1] = a.y; x[j*4+2] = b.x; x[j*4+3] = b.y;
        *(float2*)(out + row0*320 + j*8 + 2*q)     = a;
        *(float2*)(out + (row0+8)*320 + j*8 + 2*q) = b;
    }

    #pragma unroll 1
    for (int s = 0; s < TPTS - 1; s++){
        const float t0 = tspan[s], t1 = tspan[s+1];
        const float dt = t1 - t0;
        #pragma unroll
        for (int c = 0; c < 16; c++) ksum[c] = 0.f;

        #pragma unroll 1
        for (int sub = 0; sub < 4; sub++){
            const float nc   = (sub == 0) ? 0.f : ((sub == 3) ? dt : 0.5f*dt);
            const float tcur = t0 + nc;

            // pack xin A-fragments (k = 0..31) + t fragment (k=32..47)
            u32 XA[8], TF[4];
            #pragma unroll
            for (int jj = 0; jj < 2; jj++){
                int j0 = jj*2, j1 = jj*2+1;
                XA[jj*4+0] = f2h2(fmaf(nc, kk[j0*4+0], x[j0*4+0]), fmaf(nc, kk[j0*4+1], x[j0*4+1]));
                XA[jj*4+1] = f2h2(fmaf(nc, kk[j0*4+2], x[j0*4+2]), fmaf(nc, kk[j0*4+3], x[j0*4+3]));
                XA[jj*4+2] = f2h2(fmaf(nc, kk[j1*4+0], x[j1*4+0]), fmaf(nc, kk[j1*4+1], x[j1*4+1]));
                XA[jj*4+3] = f2h2(fmaf(nc, kk[j1*4+2], x[j1*4+2]), fmaf(nc, kk[j1*4+3], x[j1*4+3]));
            }
            {
                u32 th = (q == 0) ? f2h2(tcur, 0.f) : 0u;
                TF[0] = th; TF[1] = th; TF[2] = 0u; TF[3] = 0u;
            }

            float dxs[16];
            #pragma unroll
            for (int c = 0; c < 16; c++) dxs[c] = 0.f;

            u32 HA[16];

            #pragma unroll 1
            for (int e = 0; e < 8; e++){
                asm volatile("cp.async.wait_group 0;" ::: "memory");
                __syncthreads();
                u32 wbn = sb + (u32)(((e+1) & 1) * EXPW);
                stage_expert(wbn, (e+1) & 7, tid, b1, b2, b3);
                const char* wb = smem + (e & 1) * EXPW;

                // ---- L1: N=64, K=48 (X,X,T)
                float acc[32];
                #pragma unroll
                for (int i = 0; i < 32; i++) acc[i] = 0.f;
                #pragma unroll
                for (int j = 0; j < 8; j++){
                    uint2 bb;
                    bb = *(const uint2*)(wb + SW1F + (0*8+j)*256 + lane*8);
                    MMA4(&acc[j*4], XA[0],XA[1],XA[2],XA[3], bb);
                    bb = *(const uint2*)(wb + SW1F + (1*8+j)*256 + lane*8);
                    MMA4(&acc[j*4], XA[4],XA[5],XA[6],XA[7], bb);
                    bb = *(const uint2*)(wb + SW1F + (2*8+j)*256 + lane*8);
                    MMA4(&acc[j*4], TF[0],TF[1],TF[2],TF[3], bb);
                }
                EPI64(acc, wb + SB1, HA);

                // ---- L2: N=64, K=64
                #pragma unroll
                for (int i = 0; i < 32; i++) acc[i] = 0.f;
                #pragma unroll
                for (int j = 0; j < 8; j++){
                    #pragma unroll
                    for (int ks = 0; ks < 4; ks++){
                        uint2 bb = *(const uint2*)(wb + SW2F + (ks*8+j)*256 + lane*8);
                        MMA4(&acc[j*4], HA[ks*4+0],HA[ks*4+1],HA[ks*4+2],HA[ks*4+3], bb);
                    }
                }
                EPI64(acc, wb + SB2, HA);

                // ---- L3: N=32, K=64
                float a3[16];
                #pragma unroll
                for (int i = 0; i < 16; i++) a3[i] = 0.f;
                #pragma unroll
                for (int j = 0; j < 4; j++){
                    #pragma unroll
                    for (int ks = 0; ks < 4; ks++){
                        uint2 bb = *(const uint2*)(wb + SW3F + (ks*4+j)*256 + lane*8);
                        MMA4(&a3[j*4], HA[ks*4+0],HA[ks*4+1],HA[ks*4+2],HA[ks*4+3], bb);
                    }
                }
                {
                    const float* b3p = (const float*)(wb + SB3);
                    u32 fr[8];
                    #pragma unroll
                    for (int j = 0; j < 4; j++){
                        float2 bv = *(const float2*)(b3p + j*8 + 2*q);
                        float c0 = a3[j*4+0] + bv.x, c1 = a3[j*4+1] + bv.y;
                        float c2 = a3[j*4+2] + bv.x, c3 = a3[j*4+3] + bv.y;
                        dxs[j*4+0] += c0; dxs[j*4+1] += c1; dxs[j*4+2] += c2; dxs[j*4+3] += c3;
                        fr[j*2+0] = f2h2(c0, c1); fr[j*2+1] = f2h2(c2, c3);
                    }
                    uint4* fp = (uint4*)(smem + SFBASE + warp*8192 + e*1024 + lane*32);
                    fp[0] = make_uint4(fr[0], fr[1], fr[2], fr[3]);
                    fp[1] = make_uint4(fr[4], fr[5], fr[6], fr[7]);
                }
            } // experts

            // ---- gating GEMM1: A = [xin | dx_mean], N=64, K=64
            u32 DXF[8];
            #pragma unroll
            for (int jj = 0; jj < 2; jj++){
                int j0 = jj*2, j1 = jj*2+1;
                DXF[jj*4+0] = f2h2(dxs[j0*4+0]*0.125f, dxs[j0*4+1]*0.125f);
                DXF[jj*4+1] = f2h2(dxs[j0*4+2]*0.125f, dxs[j0*4+3]*0.125f);
                DXF[jj*4+2] = f2h2(dxs[j1*4+0]*0.125f, dxs[j1*4+1]*0.125f);
                DXF[jj*4+3] = f2h2(dxs[j1*4+2]*0.125f, dxs[j1*4+3]*0.125f);
            }
            {
                float acc[32];
                #pragma unroll
                for (int i = 0; i < 32; i++) acc[i] = 0.f;
                #pragma unroll
                for (int j = 0; j < 8; j++){
                    uint2 bb;
                    bb = *(const uint2*)(smem + SGW1F + (0*8+j)*256 + lane*8);
                    MMA4(&acc[j*4], XA[0],XA[1],XA[2],XA[3], bb);
                    bb = *(const uint2*)(smem + SGW1F + (1*8+j)*256 + lane*8);
                    MMA4(&acc[j*4], XA[4],XA[5],XA[6],XA[7], bb);
                    bb = *(const uint2*)(smem + SGW1F + (2*8+j)*256 + lane*8);
                    MMA4(&acc[j*4], DXF[0],DXF[1],DXF[2],DXF[3], bb);
                    bb = *(const uint2*)(smem + SGW1F + (3*8+j)*256 + lane*8);
                    MMA4(&acc[j*4], DXF[4],DXF[5],DXF[6],DXF[7], bb);
                }
                EPI64(acc, smem + SGB1, HA);
            }
            // ---- gating GEMM2: N=8 logits + softmax
            float w0, w1, w80, w81;
            {
                float z[4];
                #pragma unroll
                for (int i = 0; i < 4; i++) z[i] = 0.f;
                #pragma unroll
                for (int ks = 0; ks < 4; ks++){
                    uint2 bb = *(const uint2*)(smem + SGW2F + ks*256 + lane*8);
                    MMA4(z, HA[ks*4+0],HA[ks*4+1],HA[ks*4+2],HA[ks*4+3], bb);
                }
                float2 bv = *(const float2*)((const float*)(smem + SGB2) + 2*q);
                z[0] += bv.x; z[1] += bv.y; z[2] += bv.x; z[3] += bv.y;
                // softmax over 8 experts (2 local + quad lanes)
                float m0 = fmaxf(z[0], z[1]);
                m0 = fmaxf(m0, __shfl_xor_sync(0xffffffffu, m0, 1));
                m0 = fmaxf(m0, __shfl_xor_sync(0xffffffffu, m0, 2));
                float e0 = exp_fast(z[0]-m0), e1 = exp_fast(z[1]-m0);
                float s0 = e0 + e1;
                s0 += __shfl_xor_sync(0xffffffffu, s0, 1);
                s0 += __shfl_xor_sync(0xffffffffu, s0, 2);
                float i0 = rcp_fast(s0);
                w0 = e0*i0; w1 = e1*i0;
                float m1 = fmaxf(z[2], z[3]);
                m1 = fmaxf(m1, __shfl_xor_sync(0xffffffffu, m1, 1));
                m1 = fmaxf(m1, __shfl_xor_sync(0xffffffffu, m1, 2));
                float e2 = exp_fast(z[2]-m1), e3 = exp_fast(z[3]-m1);
                float s1 = e2 + e3;
                s1 += __shfl_xor_sync(0xffffffffu, s1, 1);
                s1 += __shfl_xor_sync(0xffffffffu, s1, 2);
                float i1 = rcp_fast(s1);
                w80 = e2*i1; w81 = e3*i1;
            }
            // publish weights, gather rows
            {
                float* wp = (float*)(smem + SWGTO + warp*512);
                *(float2*)(wp + g*8 + 2*q)     = make_float2(w0, w1);
                *(float2*)(wp + (g+8)*8 + 2*q) = make_float2(w80, w81);
            }
            __syncwarp();
            float wA[8], wB[8];
            {
                const float* wp = (const float*)(smem + SWGTO + warp*512);
                float4 a0 = *(const float4*)(wp + g*8),     a1 = *(const float4*)(wp + g*8 + 4);
                float4 c0 = *(const float4*)(wp + (g+8)*8), c1 = *(const float4*)(wp + (g+8)*8 + 4);
                wA[0]=a0.x; wA[1]=a0.y; wA[2]=a0.z; wA[3]=a0.w; wA[4]=a1.x; wA[5]=a1.y; wA[6]=a1.z; wA[7]=a1.w;
                wB[0]=c0.x; wB[1]=c0.y; wB[2]=c0.z; wB[3]=c0.w; wB[4]=c1.x; wB[5]=c1.y; wB[6]=c1.z; wB[7]=c1.w;
            }
            // combine k = sum_e wgt[e] * f_e (per-lane-private F slots)
            #pragma unroll
            for (int c = 0; c < 16; c++) kk[c] = 0.f;
            #pragma unroll
            for (int e2 = 0; e2 < 8; e2++){
                const uint4* fp = (const uint4*)(smem + SFBASE + warp*8192 + e2*1024 + lane*32);
                uint4 fa = fp[0], fb = fp[1];
                float2 t;
                t = h22f2(fa.x); kk[0] = fmaf(wA[e2], t.x, kk[0]); kk[1] = fmaf(wA[e2], t.y, kk[1]);
                t = h22f2(fa.y); kk[2] = fmaf(wB[e2], t.x, kk[2]); kk[3] = fmaf(wB[e2], t.y, kk[3]);
                t = h22f2(fa.z); kk[4] = fmaf(wA[e2], t.x, kk[4]); kk[5] = fmaf(wA[e2], t.y, kk[5]);
                t = h22f2(fa.w); kk[6] = fmaf(wB[e2], t.x, kk[6]); kk[7] = fmaf(wB[e2], t.y, kk[7]);
                t = h22f2(fb.x); kk[8] = fmaf(wA[e2], t.x, kk[8]); kk[9] = fmaf(wA[e2], t.y, kk[9]);
                t = h22f2(fb.y); kk[10] = fmaf(wB[e2], t.x, kk[10]); kk[11] = fmaf(wB[e2], t.y, kk[11]);
                t = h22f2(fb.z); kk[12] = fmaf(wA[e2], t.x, kk[12]); kk[13] = fmaf(wA[e2], t.y, kk[13]);
                t = h22f2(fb.w); kk[14] = fmaf(wB[e2], t.x, kk[14]); kk[15] = fmaf(wB[e2], t.y, kk[15]);
            }
            const float ws = (sub == 0 || sub == 3) ? 1.f : 2.f;
            #pragma unroll
            for (int c = 0; c < 16; c++) ksum[c] = fmaf(ws, kk[c], ksum[c]);
        } // sub

        const float sc = dt * (1.f/6.f);
        #pragma unroll
        for (int c = 0; c < 16; c++) x[c] = fmaf(sc, ksum[c], x[c]);
        #pragma unroll
        for (int j = 0; j < 4; j++){
            *(float2*)(out + row0*320 + (s+1)*32 + j*8 + 2*q)     = make_float2(x[j*4+0], x[j*4+1]);
            *(float2*)(out + (row0+8)*320 + (s+1)*32 + j*8 + 2*q) = make_float2(x[j*4+2], x[j*4+3]);
        }
    } // step
}

extern "C" void kernel_launch(void* const* d_in, const int* in_sizes, int n_in,
                              void* d_out, int out_size)
{
    (void)in_sizes; (void)n_in; (void)out_size;
    conv_weights<<<128, 256>>>(
        (const float*)d_in[2],  (const float*)d_in[4], (const float*)d_in[6],
        (const float*)d_in[8],  (const float*)d_in[10]);
    cudaFuncSetAttribute(ameode_mma, cudaFuncAttributeMaxDynamicSharedMemorySize, SMEM_BYTES);
    ameode_mma<<<128, CTA, SMEM_BYTES>>>(
        (const float*)d_in[0],  (const float*)d_in[1],
        (const float*)d_in[3],  (const float*)d_in[5], (const float*)d_in[7],
        (const float*)d_in[9],  (const float*)d_in[11],
        (float*)d_out);
}

// round 12
// speedup vs baseline: 9.2697x; 1.5826x over previous
#include <cuda_runtime.h>
#include <cuda_fp16.h>

typedef unsigned int u32;

#define TPTS 10
#define CTA 256

// ---- smem byte offsets ----
#define EXPW   19200
#define SW1F   0
#define SW2F   6144
#define SW3F   14336
#define SB1    18432
#define SB2    18688
#define SB3    18944
#define SGW1F  38400
#define SGW2F  46592
#define SGB1   47616
#define SGB2   47872
#define SFBASE 48128      // F[warp][e][lane][32B]
#define SWGTO  113664     // wgt[warp][16][8] f32
#define SMEM_BYTES 117760

// weights pre-arranged in B-fragment register order
__device__ __align__(16) u32 g_W1F[8*3*8*64];
__device__ __align__(16) u32 g_W2F[8*4*8*64];
__device__ __align__(16) u32 g_W3F[8*4*4*64];
__device__ __align__(16) u32 g_GW1F[4*8*64];
__device__ __align__(16) u32 g_GW2F[4*64];

static __device__ __forceinline__ u32 f2h2(float lo, float hi){
    u32 r; asm("cvt.rn.f16x2.f32 %0, %2, %1;" : "=r"(r) : "f"(lo), "f"(hi)); return r;
}
static __device__ __forceinline__ float2 h22f2(u32 h){
    __half2 v = *(__half2*)&h; return __half22float2(v);
}
static __device__ __forceinline__ u32 tanh_h2(u32 h){
    u32 r; asm("tanh.approx.f16x2 %0,%1;" : "=r"(r) : "r"(h)); return r;
}
static __device__ __forceinline__ float exp_fast(float x){
    float e; asm("ex2.approx.f32 %0,%1;" : "=f"(e) : "f"(x * 1.4426950408889634f)); return e;
}
static __device__ __forceinline__ float rcp_fast(float x){
    float r; asm("rcp.approx.f32 %0,%1;" : "=f"(r) : "f"(x)); return r;
}

#define MMA4(d, a0,a1,a2,a3, b) \
    asm volatile("mma.sync.aligned.m16n8k16.row.col.f32.f16.f16.f32 " \
        "{%0,%1,%2,%3},{%4,%5,%6,%7},{%8,%9},{%0,%1,%2,%3};" \
        : "+f"((d)[0]),"+f"((d)[1]),"+f"((d)[2]),"+f"((d)[3]) \
        : "r"(a0),"r"(a1),"r"(a2),"r"(a3),"r"((b).x),"r"((b).y))

#define MMA4_INIT(d, a0,a1,a2,a3, b) \
    asm volatile("mma.sync.aligned.m16n8k16.row.col.f32.f16.f16.f32 " \
        "{%0,%1,%2,%3},{%4,%5,%6,%7},{%8,%9},{%10,%10,%10,%10};" \
        : "=f"((d)[0]),"=f"((d)[1]),"=f"((d)[2]),"=f"((d)[3]) \
        : "r"(a0),"r"(a1),"r"(a2),"r"(a3),"r"((b).x),"r"((b).y),"f"(0.f))

static __device__ __forceinline__ void stage16(u32 dst, const char* src, int n16, int tid){
    for (int i = tid; i < n16; i += CTA)
        asm volatile("cp.async.cg.shared.global [%0],[%1],16;"
                     :: "r"(dst + (u32)i*16), "l"(src + i*16));
}
static __device__ __forceinline__ void stage_expert(u32 sbuf, int e, int tid,
                                                    const float* b1, const float* b2, const float* b3){
    stage16(sbuf + SW1F, (const char*)g_W1F + e*6144, 384, tid);
    stage16(sbuf + SW2F, (const char*)g_W2F + e*8192, 512, tid);
    stage16(sbuf + SW3F, (const char*)g_W3F + e*4096, 256, tid);
    stage16(sbuf + SB1, (const char*)(b1 + e*64), 16, tid);
    stage16(sbuf + SB2, (const char*)(b2 + e*64), 16, tid);
    stage16(sbuf + SB3, (const char*)(b3 + e*32),  8, tid);
    asm volatile("cp.async.commit_group;" ::: "memory");
}

// epilogue for N=64 layers: bias add (fp32) -> fp16 pack -> tanh.f16x2 -> A-frags
#define EPI64(acc, biasptr, HA) { \
    const float* _b = (const float*)(biasptr); \
    _Pragma("unroll") \
    for (int j = 0; j < 8; j++){ \
        float2 bv = *(const float2*)(_b + j*8 + 2*q); \
        u32 p0 = f2h2((acc)[j*4+0] + bv.x, (acc)[j*4+1] + bv.y); \
        u32 p1 = f2h2((acc)[j*4+2] + bv.x, (acc)[j*4+3] + bv.y); \
        (HA)[(j>>1)*4 + (j&1)*2 + 0] = tanh_h2(p0); \
        (HA)[(j>>1)*4 + (j&1)*2 + 1] = tanh_h2(p1); \
    } }

// ---------------- weight frag-order pre-kernel ----------------
__global__ void conv_weights(const float* __restrict__ W1, const float* __restrict__ W2,
                             const float* __restrict__ W3, const float* __restrict__ Gw1,
                             const float* __restrict__ Gw2){
    int i0 = blockIdx.x*blockDim.x + threadIdx.x, st = gridDim.x*blockDim.x;
    for (int i = i0; i < 8*3*8*64; i += st){
        int r = i & 1, t = i >> 1, l = t & 31; t >>= 5;
        int j = t & 7; t >>= 3; int ks = t % 3, e = t / 3;
        int k = ks*16 + (l&3)*2 + r*8, n = j*8 + (l>>2);
        float lo = (k   < 33) ? W1[e*2112 + k*64 + n]     : 0.f;
        float hi = (k+1 < 33) ? W1[e*2112 + (k+1)*64 + n] : 0.f;
        __half2 h = __floats2half2_rn(lo, hi);
        g_W1F[i] = *(u32*)&h;
    }
    for (int i = i0; i < 8*4*8*64; i += st){
        int r = i & 1, t = i >> 1, l = t & 31; t >>= 5;
        int j = t & 7; t >>= 3; int ks = t & 3, e = t >> 2;
        int k = ks*16 + (l&3)*2 + r*8, n = j*8 + (l>>2);
        __half2 h = __floats2half2_rn(W2[e*4096 + k*64 + n], W2[e*4096 + (k+1)*64 + n]);
        g_W2F[i] = *(u32*)&h;
    }
    for (int i = i0; i < 8*4*4*64; i += st){
        int r = i & 1, t = i >> 1, l = t & 31; t >>= 5;
        int j = t & 3; t >>= 2; int ks = t & 3, e = t >> 2;
        int k = ks*16 + (l&3)*2 + r*8, n = j*8 + (l>>2);
        __half2 h = __floats2half2_rn(W3[e*2048 + k*32 + n], W3[e*2048 + (k+1)*32 + n]);
        g_W3F[i] = *(u32*)&h;
    }
    for (int i = i0; i < 4*8*64; i += st){
        int r = i & 1, t = i >> 1, l = t & 31; t >>= 5;
        int j = t & 7, ks = t >> 3;
        int k = ks*16 + (l&3)*2 + r*8, n = j*8 + (l>>2);
        __half2 h = __floats2half2_rn(Gw1[k*64 + n], Gw1[(k+1)*64 + n]);
        g_GW1F[i] = *(u32*)&h;
    }
    for (int i = i0; i < 4*64; i += st){
        int r = i & 1, t = i >> 1, l = t & 31; t >>= 5;
        int ks = t;
        int k = ks*16 + (l&3)*2 + r*8, n = l >> 2;
        __half2 h = __floats2half2_rn(Gw2[k*8 + n], Gw2[(k+1)*8 + n]);
        g_GW2F[i] = *(u32*)&h;
    }
}

// ---------------- main kernel ----------------
__global__ void __launch_bounds__(CTA, 1)
ameode_mma(const float* __restrict__ x0, const float* __restrict__ tspan,
           const float* __restrict__ b1, const float* __restrict__ b2, const float* __restrict__ b3,
           const float* __restrict__ Gb1, const float* __restrict__ Gb2,
           float* __restrict__ out)
{
    extern __shared__ char smem[];
    u32 sb = (u32)__cvta_generic_to_shared(smem);
    const int tid = threadIdx.x, lane = tid & 31, warp = tid >> 5;
    const int g = lane >> 2, q = lane & 3;
    const int row0 = blockIdx.x*128 + warp*16 + g;    // rows row0, row0+8

    // stage gate weights + expert 0 (single commit group)
    stage16(sb + SGW1F, (const char*)g_GW1F, 512, tid);
    stage16(sb + SGW2F, (const char*)g_GW2F, 64, tid);
    stage16(sb + SGB1, (const char*)Gb1, 16, tid);
    stage16(sb + SGB2, (const char*)Gb2, 2, tid);
    stage_expert(sb, 0, tid, b1, b2, b3);

    float x[16], ksum[16], kk[16];
    #pragma unroll
    for (int c = 0; c < 16; c++) kk[c] = 0.f;
    #pragma unroll
    for (int j = 0; j < 4; j++){
        float2 a = *(const float2*)(x0 + row0*32 + j*8 + 2*q);
        float2 b = *(const float2*)(x0 + (row0+8)*32 + j*8 + 2*q);
        x[j*4+0] = a.x; x[j*4+1] = a.y; x[j*4+2] = b.x; x[j*4+3] = b.y;
        *(float2*)(out + row0*320 + j*8 + 2*q)     = a;
        *(float2*)(out + (row0+8)*320 + j*8 + 2*q) = b;
    }

    #pragma unroll 1
    for (int s = 0; s < TPTS - 1; s++){
        const float t0 = tspan[s], t1 = tspan[s+1];
        const float dt = t1 - t0;
        #pragma unroll
        for (int c = 0; c < 16; c++) ksum[c] = 0.f;

        #pragma unroll 1
        for (int sub = 0; sub < 4; sub++){
            const float nc   = (sub == 0) ? 0.f : ((sub == 3) ? dt : 0.5f*dt);
            const float tcur = t0 + nc;

            // pack xin A-fragments (k = 0..31) + t fragment (k=32..47)
            u32 XA[8], TF[4];
            #pragma unroll
            for (int jj = 0; jj < 2; jj++){
                int j0 = jj*2, j1 = jj*2+1;
                XA[jj*4+0] = f2h2(fmaf(nc, kk[j0*4+0], x[j0*4+0]), fmaf(nc, kk[j0*4+1], x[j0*4+1]));
                XA[jj*4+1] = f2h2(fmaf(nc, kk[j0*4+2], x[j0*4+2]), fmaf(nc, kk[j0*4+3], x[j0*4+3]));
                XA[jj*4+2] = f2h2(fmaf(nc, kk[j1*4+0], x[j1*4+0]), fmaf(nc, kk[j1*4+1], x[j1*4+1]));
                XA[jj*4+3] = f2h2(fmaf(nc, kk[j1*4+2], x[j1*4+2]), fmaf(nc, kk[j1*4+3], x[j1*4+3]));
            }
            {
                u32 th = (q == 0) ? f2h2(tcur, 0.f) : 0u;
                TF[0] = th; TF[1] = th; TF[2] = 0u; TF[3] = 0u;
            }

            float dxs[16];
            #pragma unroll
            for (int c = 0; c < 16; c++) dxs[c] = 0.f;

            u32 HA[16];

            #pragma unroll 1
            for (int e = 0; e < 8; e++){
                asm volatile("cp.async.wait_group 0;" ::: "memory");
                __syncthreads();
                u32 wbn = sb + (u32)(((e+1) & 1) * EXPW);
                stage_expert(wbn, (e+1) & 7, tid, b1, b2, b3);
                const char* wb = smem + (e & 1) * EXPW;

                // ---- L1: N=64, K=48 (X,X,T)
                float acc[32];
                #pragma unroll
                for (int j = 0; j < 8; j++){
                    uint2 bb;
                    bb = *(const uint2*)(wb + SW1F + (0*8+j)*256 + lane*8);
                    MMA4_INIT(&acc[j*4], XA[0],XA[1],XA[2],XA[3], bb);
                    bb = *(const uint2*)(wb + SW1F + (1*8+j)*256 + lane*8);
                    MMA4(&acc[j*4], XA[4],XA[5],XA[6],XA[7], bb);
                    bb = *(const uint2*)(wb + SW1F + (2*8+j)*256 + lane*8);
                    MMA4(&acc[j*4], TF[0],TF[1],TF[2],TF[3], bb);
                }
                EPI64(acc, wb + SB1, HA);

                // ---- L2: N=64, K=64
                #pragma unroll
                for (int j = 0; j < 8; j++){
                    uint2 bb = *(const uint2*)(wb + SW2F + (0*8+j)*256 + lane*8);
                    MMA4_INIT(&acc[j*4], HA[0],HA[1],HA[2],HA[3], bb);
                    #pragma unroll
                    for (int ks = 1; ks < 4; ks++){
                        bb = *(const uint2*)(wb + SW2F + (ks*8+j)*256 + lane*8);
                        MMA4(&acc[j*4], HA[ks*4+0],HA[ks*4+1],HA[ks*4+2],HA[ks*4+3], bb);
                    }
                }
                EPI64(acc, wb + SB2, HA);

                // ---- L3: N=32, K=64
                float a3[16];
                #pragma unroll
                for (int j = 0; j < 4; j++){
                    uint2 bb = *(const uint2*)(wb + SW3F + (0*4+j)*256 + lane*8);
                    MMA4_INIT(&a3[j*4], HA[0],HA[1],HA[2],HA[3], bb);
                    #pragma unroll
                    for (int ks = 1; ks < 4; ks++){
                        bb = *(const uint2*)(wb + SW3F + (ks*4+j)*256 + lane*8);
                        MMA4(&a3[j*4], HA[ks*4+0],HA[ks*4+1],HA[ks*4+2],HA[ks*4+3], bb);
                    }
                }
                {
                    const float* b3p = (const float*)(wb + SB3);
                    u32 fr[8];
                    #pragma unroll
                    for (int j = 0; j < 4; j++){
                        float2 bv = *(const float2*)(b3p + j*8 + 2*q);
                        float c0 = a3[j*4+0] + bv.x, c1 = a3[j*4+1] + bv.y;
                        float c2 = a3[j*4+2] + bv.x, c3 = a3[j*4+3] + bv.y;
                        dxs[j*4+0] += c0; dxs[j*4+1] += c1; dxs[j*4+2] += c2; dxs[j*4+3] += c3;
                        fr[j*2+0] = f2h2(c0, c1); fr[j*2+1] = f2h2(c2, c3);
                    }
                    uint4* fp = (uint4*)(smem + SFBASE + warp*8192 + e*1024 + lane*32);
                    fp[0] = make_uint4(fr[0], fr[1], fr[2], fr[3]);
                    fp[1] = make_uint4(fr[4], fr[5], fr[6], fr[7]);
                }
            } // experts

            // ---- gating GEMM1: A = [xin | dx_mean], N=64, K=64
            u32 DXF[8];
            #pragma unroll
            for (int jj = 0; jj < 2; jj++){
                int j0 = jj*2, j1 = jj*2+1;
                DXF[jj*4+0] = f2h2(dxs[j0*4+0]*0.125f, dxs[j0*4+1]*0.125f);
                DXF[jj*4+1] = f2h2(dxs[j0*4+2]*0.125f, dxs[j0*4+3]*0.125f);
                DXF[jj*4+2] = f2h2(dxs[j1*4+0]*0.125f, dxs[j1*4+1]*0.125f);
                DXF[jj*4+3] = f2h2(dxs[j1*4+2]*0.125f, dxs[j1*4+3]*0.125f);
            }
            {
                float acc[32];
                #pragma unroll
                for (int j = 0; j < 8; j++){
                    uint2 bb;
                    bb = *(const uint2*)(smem + SGW1F + (0*8+j)*256 + lane*8);
                    MMA4_INIT(&acc[j*4], XA[0],XA[1],XA[2],XA[3], bb);
                    bb = *(const uint2*)(smem + SGW1F + (1*8+j)*256 + lane*8);
                    MMA4(&acc[j*4], XA[4],XA[5],XA[6],XA[7], bb);
                    bb = *(const uint2*)(smem + SGW1F + (2*8+j)*256 + lane*8);
                    MMA4(&acc[j*4], DXF[0],DXF[1],DXF[2],DXF[3], bb);
                    bb = *(const uint2*)(smem + SGW1F + (3*8+j)*256 + lane*8);
                    MMA4(&acc[j*4], DXF[4],DXF[5],DXF[6],DXF[7], bb);
                }
                EPI64(acc, smem + SGB1, HA);
            }
            // ---- gating GEMM2: N=8 logits + softmax
            float w0, w1, w80, w81;
            {
                float z[4];
                uint2 bb = *(const uint2*)(smem + SGW2F + 0*256 + lane*8);
                MMA4_INIT(z, HA[0],HA[1],HA[2],HA[3], bb);
                #pragma unroll
                for (int ks = 1; ks < 4; ks++){
                    bb = *(const uint2*)(smem + SGW2F + ks*256 + lane*8);
                    MMA4(z, HA[ks*4+0],HA[ks*4+1],HA[ks*4+2],HA[ks*4+3], bb);
                }
                float2 bv = *(const float2*)((const float*)(smem + SGB2) + 2*q);
                z[0] += bv.x; z[1] += bv.y; z[2] += bv.x; z[3] += bv.y;
                float m0 = fmaxf(z[0], z[1]);
                m0 = fmaxf(m0, __shfl_xor_sync(0xffffffffu, m0, 1));
                m0 = fmaxf(m0, __shfl_xor_sync(0xffffffffu, m0, 2));
                float e0 = exp_fast(z[0]-m0), e1 = exp_fast(z[1]-m0);
                float s0 = e0 + e1;
                s0 += __shfl_xor_sync(0xffffffffu, s0, 1);
                s0 += __shfl_xor_sync(0xffffffffu, s0, 2);
                float i0 = rcp_fast(s0);
                w0 = e0*i0; w1 = e1*i0;
                float m1 = fmaxf(z[2], z[3]);
                m1 = fmaxf(m1, __shfl_xor_sync(0xffffffffu, m1, 1));
                m1 = fmaxf(m1, __shfl_xor_sync(0xffffffffu, m1, 2));
                float e2 = exp_fast(z[2]-m1), e3 = exp_fast(z[3]-m1);
                float s1 = e2 + e3;
                s1 += __shfl_xor_sync(0xffffffffu, s1, 1);
                s1 += __shfl_xor_sync(0xffffffffu, s1, 2);
                float i1 = rcp_fast(s1);
                w80 = e2*i1; w81 = e3*i1;
            }
            // publish weights, gather rows
            {
                float* wp = (float*)(smem + SWGTO + warp*512);
                *(float2*)(wp + g*8 + 2*q)     = make_float2(w0, w1);
                *(float2*)(wp + (g+8)*8 + 2*q) = make_float2(w80, w81);
            }
            __syncwarp();
            float wA[8], wB[8];
            {
                const float* wp = (const float*)(smem + SWGTO + warp*512);
                float4 a0 = *(const float4*)(wp + g*8),     a1 = *(const float4*)(wp + g*8 + 4);
                float4 c0 = *(const float4*)(wp + (g+8)*8), c1 = *(const float4*)(wp + (g+8)*8 + 4);
                wA[0]=a0.x; wA[1]=a0.y; wA[2]=a0.z; wA[3]=a0.w; wA[4]=a1.x; wA[5]=a1.y; wA[6]=a1.z; wA[7]=a1.w;
                wB[0]=c0.x; wB[1]=c0.y; wB[2]=c0.z; wB[3]=c0.w; wB[4]=c1.x; wB[5]=c1.y; wB[6]=c1.z; wB[7]=c1.w;
            }
            // combine k = sum_e wgt[e] * f_e (per-lane-private F slots)
            #pragma unroll
            for (int c = 0; c < 16; c++) kk[c] = 0.f;
            #pragma unroll
            for (int e2 = 0; e2 < 8; e2++){
                const uint4* fp = (const uint4*)(smem + SFBASE + warp*8192 + e2*1024 + lane*32);
                uint4 fa = fp[0], fb = fp[1];
                float2 t;
                t = h22f2(fa.x); kk[0] = fmaf(wA[e2], t.x, kk[0]); kk[1] = fmaf(wA[e2], t.y, kk[1]);
                t = h22f2(fa.y); kk[2] = fmaf(wB[e2], t.x, kk[2]); kk[3] = fmaf(wB[e2], t.y, kk[3]);
                t = h22f2(fa.z); kk[4] = fmaf(wA[e2], t.x, kk[4]); kk[5] = fmaf(wA[e2], t.y, kk[5]);
                t = h22f2(fa.w); kk[6] = fmaf(wB[e2], t.x, kk[6]); kk[7] = fmaf(wB[e2], t.y, kk[7]);
                t = h22f2(fb.x); kk[8] = fmaf(wA[e2], t.x, kk[8]); kk[9] = fmaf(wA[e2], t.y, kk[9]);
                t = h22f2(fb.y); kk[10] = fmaf(wB[e2], t.x, kk[10]); kk[11] = fmaf(wB[e2], t.y, kk[11]);
                t = h22f2(fb.z); kk[12] = fmaf(wA[e2], t.x, kk[12]); kk[13] = fmaf(wA[e2], t.y, kk[13]);
                t = h22f2(fb.w); kk[14] = fmaf(wB[e2], t.x, kk[14]); kk[15] = fmaf(wB[e2], t.y, kk[15]);
            }
            const float ws = (sub == 0 || sub == 3) ? 1.f : 2.f;
            #pragma unroll
            for (int c = 0; c < 16; c++) ksum[c] = fmaf(ws, kk[c], ksum[c]);
        } // sub

        const float sc = dt * (1.f/6.f);
        #pragma unroll
        for (int c = 0; c < 16; c++) x[c] = fmaf(sc, ksum[c], x[c]);
        #pragma unroll
        for (int j = 0; j < 4; j++){
            *(float2*)(out + row0*320 + (s+1)*32 + j*8 + 2*q)     = make_float2(x[j*4+0], x[j*4+1]);
            *(float2*)(out + (row0+8)*320 + (s+1)*32 + j*8 + 2*q) = make_float2(x[j*4+2], x[j*4+3]);
        }
    } // step
}

extern "C" void kernel_launch(void* const* d_in, const int* in_sizes, int n_in,
                              void* d_out, int out_size)
{
    (void)in_sizes; (void)n_in; (void)out_size;
    conv_weights<<<128, 256>>>(
        (const float*)d_in[2],  (const float*)d_in[4], (const float*)d_in[6],
        (const float*)d_in[8],  (const float*)d_in[10]);
    cudaFuncSetAttribute(ameode_mma, cudaFuncAttributeMaxDynamicSharedMemorySize, SMEM_BYTES);
    ameode_mma<<<128, CTA, SMEM_BYTES>>>(
        (const float*)d_in[0],  (const float*)d_in[1],
        (const float*)d_in[3],  (const float*)d_in[5], (const float*)d_in[7],
        (const float*)d_in[9],  (const float*)d_in[11],
        (float*)d_out);
}

// round 14
// speedup vs baseline: 11.4341x; 1.2335x over previous
#include <cuda_runtime.h>
#include <cuda_fp16.h>

typedef unsigned int u32;

#define TPTS 10
#define CTA 256

// ---- smem byte offsets ----
// 8 resident expert buffers, stride 19200:
//   W1F 0 (6144) | W2F 6144 (8192) | W3F 14336 (4096) | B1 18432 | B2 18688 | B3 18944
#define EXPW   19200
#define SW1F   0
#define SW2F   6144
#define SW3F   14336
#define SB1    18432
#define SB2    18688
#define SB3    18944
#define SGW1F  153600     // 8192
#define SGW2F  161792     // 1024
#define SGB1   162816     // 256
#define SGB2   163072     // 32
#define SFBASE 163104     // F[warp][e][lane][32B] = 65536
#define SMEM_BYTES 228640

// weights pre-arranged in B-fragment register order
__device__ __align__(16) u32 g_W1F[8*3*8*64];
__device__ __align__(16) u32 g_W2F[8*4*8*64];
__device__ __align__(16) u32 g_W3F[8*4*4*64];
__device__ __align__(16) u32 g_GW1F[4*8*64];
__device__ __align__(16) u32 g_GW2F[4*64];

static __device__ __forceinline__ u32 f2h2(float lo, float hi){
    u32 r; asm("cvt.rn.f16x2.f32 %0, %2, %1;" : "=r"(r) : "f"(lo), "f"(hi)); return r;
}
static __device__ __forceinline__ float2 h22f2(u32 h){
    __half2 v = *(__half2*)&h; return __half22float2(v);
}
static __device__ __forceinline__ u32 tanh_h2(u32 h){
    u32 r; asm("tanh.approx.f16x2 %0,%1;" : "=r"(r) : "r"(h)); return r;
}
static __device__ __forceinline__ float exp_fast(float x){
    float e; asm("ex2.approx.f32 %0,%1;" : "=f"(e) : "f"(x * 1.4426950408889634f)); return e;
}
static __device__ __forceinline__ float rcp_fast(float x){
    float r; asm("rcp.approx.f32 %0,%1;" : "=f"(r) : "f"(x)); return r;
}

#define MMA4(d, a0,a1,a2,a3, b) \
    asm volatile("mma.sync.aligned.m16n8k16.row.col.f32.f16.f16.f32 " \
        "{%0,%1,%2,%3},{%4,%5,%6,%7},{%8,%9},{%0,%1,%2,%3};" \
        : "+f"((d)[0]),"+f"((d)[1]),"+f"((d)[2]),"+f"((d)[3]) \
        : "r"(a0),"r"(a1),"r"(a2),"r"(a3),"r"((b).x),"r"((b).y))

#define MMA4_INIT(d, a0,a1,a2,a3, b) \
    asm volatile("mma.sync.aligned.m16n8k16.row.col.f32.f16.f16.f32 " \
        "{%0,%1,%2,%3},{%4,%5,%6,%7},{%8,%9},{%10,%10,%10,%10};" \
        : "=f"((d)[0]),"=f"((d)[1]),"=f"((d)[2]),"=f"((d)[3]) \
        : "r"(a0),"r"(a1),"r"(a2),"r"(a3),"r"((b).x),"r"((b).y),"f"(0.f))

static __device__ __forceinline__ void stage16(u32 dst, const char* src, int n16, int tid){
    for (int i = tid; i < n16; i += CTA)
        asm volatile("cp.async.cg.shared.global [%0],[%1],16;"
                     :: "r"(dst + (u32)i*16), "l"(src + i*16));
}

// epilogue for N=64 layers: bias add (fp32) -> fp16 pack -> tanh.f16x2 -> A-frags
#define EPI64(acc, biasptr, HA) { \
    const float* _b = (const float*)(biasptr); \
    _Pragma("unroll") \
    for (int j = 0; j < 8; j++){ \
        float2 bv = *(const float2*)(_b + j*8 + 2*q); \
        u32 p0 = f2h2((acc)[j*4+0] + bv.x, (acc)[j*4+1] + bv.y); \
        u32 p1 = f2h2((acc)[j*4+2] + bv.x, (acc)[j*4+3] + bv.y); \
        (HA)[(j>>1)*4 + (j&1)*2 + 0] = tanh_h2(p0); \
        (HA)[(j>>1)*4 + (j&1)*2 + 1] = tanh_h2(p1); \
    } }

// ---------------- weight frag-order pre-kernel ----------------
__global__ void conv_weights(const float* __restrict__ W1, const float* __restrict__ W2,
                             const float* __restrict__ W3, const float* __restrict__ Gw1,
                             const float* __restrict__ Gw2){
    int i0 = blockIdx.x*blockDim.x + threadIdx.x, st = gridDim.x*blockDim.x;
    for (int i = i0; i < 8*3*8*64; i += st){
        int r = i & 1, t = i >> 1, l = t & 31; t >>= 5;
        int j = t & 7; t >>= 3; int ks = t % 3, e = t / 3;
        int k = ks*16 + (l&3)*2 + r*8, n = j*8 + (l>>2);
        float lo = (k   < 33) ? W1[e*2112 + k*64 + n]     : 0.f;
        float hi = (k+1 < 33) ? W1[e*2112 + (k+1)*64 + n] : 0.f;
        __half2 h = __floats2half2_rn(lo, hi);
        g_W1F[i] = *(u32*)&h;
    }
    for (int i = i0; i < 8*4*8*64; i += st){
        int r = i & 1, t = i >> 1, l = t & 31; t >>= 5;
        int j = t & 7; t >>= 3; int ks = t & 3, e = t >> 2;
        int k = ks*16 + (l&3)*2 + r*8, n = j*8 + (l>>2);
        __half2 h = __floats2half2_rn(W2[e*4096 + k*64 + n], W2[e*4096 + (k+1)*64 + n]);
        g_W2F[i] = *(u32*)&h;
    }
    for (int i = i0; i < 8*4*4*64; i += st){
        int r = i & 1, t = i >> 1, l = t & 31; t >>= 5;
        int j = t & 3; t >>= 2; int ks = t & 3, e = t >> 2;
        int k = ks*16 + (l&3)*2 + r*8, n = j*8 + (l>>2);
        __half2 h = __floats2half2_rn(W3[e*2048 + k*32 + n], W3[e*2048 + (k+1)*32 + n]);
        g_W3F[i] = *(u32*)&h;
    }
    for (int i = i0; i < 4*8*64; i += st){
        int r = i & 1, t = i >> 1, l = t & 31; t >>= 5;
        int j = t & 7, ks = t >> 3;
        int k = ks*16 + (l&3)*2 + r*8, n = j*8 + (l>>2);
        __half2 h = __floats2half2_rn(Gw1[k*64 + n], Gw1[(k+1)*64 + n]);
        g_GW1F[i] = *(u32*)&h;
    }
    for (int i = i0; i < 4*64; i += st){
        int r = i & 1, t = i >> 1, l = t & 31; t >>= 5;
        int ks = t;
        int k = ks*16 + (l&3)*2 + r*8, n = l >> 2;
        __half2 h = __floats2half2_rn(Gw2[k*8 + n], Gw2[(k+1)*8 + n]);
        g_GW2F[i] = *(u32*)&h;
    }
}

// ---------------- main kernel ----------------
__global__ void __launch_bounds__(CTA, 1)
ameode_mma(const float* __restrict__ x0, const float* __restrict__ tspan,
           const float* __restrict__ b1, const float* __restrict__ b2, const float* __restrict__ b3,
           const float* __restrict__ Gb1, const float* __restrict__ Gb2,
           float* __restrict__ out)
{
    extern __shared__ char smem[];
    u32 sb = (u32)__cvta_generic_to_shared(smem);
    const int tid = threadIdx.x, lane = tid & 31, warp = tid >> 5;
    const int g = lane >> 2, q = lane & 3;
    const int row0 = blockIdx.x*128 + warp*16 + g;    // rows row0, row0+8

    // stage ALL 8 expert buffers + gating weights ONCE (read-only thereafter)
    #pragma unroll 1
    for (int e = 0; e < 8; e++){
        u32 bo = sb + (u32)e * EXPW;
        stage16(bo + SW1F, (const char*)g_W1F + e*6144, 384, tid);
        stage16(bo + SW2F, (const char*)g_W2F + e*8192, 512, tid);
        stage16(bo + SW3F, (const char*)g_W3F + e*4096, 256, tid);
        stage16(bo + SB1, (const char*)(b1 + e*64), 16, tid);
        stage16(bo + SB2, (const char*)(b2 + e*64), 16, tid);
        stage16(bo + SB3, (const char*)(b3 + e*32),  8, tid);
    }
    stage16(sb + SGW1F, (const char*)g_GW1F, 512, tid);
    stage16(sb + SGW2F, (const char*)g_GW2F, 64, tid);
    stage16(sb + SGB1, (const char*)Gb1, 16, tid);
    stage16(sb + SGB2, (const char*)Gb2, 2, tid);
    asm volatile("cp.async.commit_group;" ::: "memory");

    float x[16], ksum[16], kk[16];
    #pragma unroll
    for (int c = 0; c < 16; c++) kk[c] = 0.f;
    #pragma unroll
    for (int j = 0; j < 4; j++){
        float2 a = *(const float2*)(x0 + row0*32 + j*8 + 2*q);
        float2 b = *(const float2*)(x0 + (row0+8)*32 + j*8 + 2*q);
        x[j*4+0] = a.x; x[j*4+1] = a.y; x[j*4+2] = b.x; x[j*4+3] = b.y;
        *(float2*)(out + row0*320 + j*8 + 2*q)     = a;
        *(float2*)(out + (row0+8)*320 + j*8 + 2*q) = b;
    }

    asm volatile("cp.async.wait_group 0;" ::: "memory");
    __syncthreads();    // the ONLY CTA-wide barrier

    #pragma unroll 1
    for (int s = 0; s < TPTS - 1; s++){
        const float t0 = tspan[s], t1 = tspan[s+1];
        const float dt = t1 - t0;
        #pragma unroll
        for (int c = 0; c < 16; c++) ksum[c] = 0.f;

        #pragma unroll 1
        for (int sub = 0; sub < 4; sub++){
            const float nc   = (sub == 0) ? 0.f : ((sub == 3) ? dt : 0.5f*dt);
            const float tcur = t0 + nc;

            // pack xin A-fragments (k = 0..31) + t fragment (k=32..47)
            u32 XA[8], TF[4];
            #pragma unroll
            for (int jj = 0; jj < 2; jj++){
                int j0 = jj*2, j1 = jj*2+1;
                XA[jj*4+0] = f2h2(fmaf(nc, kk[j0*4+0], x[j0*4+0]), fmaf(nc, kk[j0*4+1], x[j0*4+1]));
                XA[jj*4+1] = f2h2(fmaf(nc, kk[j0*4+2], x[j0*4+2]), fmaf(nc, kk[j0*4+3], x[j0*4+3]));
                XA[jj*4+2] = f2h2(fmaf(nc, kk[j1*4+0], x[j1*4+0]), fmaf(nc, kk[j1*4+1], x[j1*4+1]));
                XA[jj*4+3] = f2h2(fmaf(nc, kk[j1*4+2], x[j1*4+2]), fmaf(nc, kk[j1*4+3], x[j1*4+3]));
            }
            {
                u32 th = (q == 0) ? f2h2(tcur, 0.f) : 0u;
                TF[0] = th; TF[1] = th; TF[2] = 0u; TF[3] = 0u;
            }

            float dxs[16];
            #pragma unroll
            for (int c = 0; c < 16; c++) dxs[c] = 0.f;

            u32 HA[16];

            #pragma unroll 1
            for (int e = 0; e < 8; e++){
                const char* wb = smem + e * EXPW;

                // ---- L1: N=64, K=48 (X,X,T)
                float acc[32];
                #pragma unroll
                for (int j = 0; j < 8; j++){
                    uint2 bb;
                    bb = *(const uint2*)(wb + SW1F + (0*8+j)*256 + lane*8);
                    MMA4_INIT(&acc[j*4], XA[0],XA[1],XA[2],XA[3], bb);
                    bb = *(const uint2*)(wb + SW1F + (1*8+j)*256 + lane*8);
                    MMA4(&acc[j*4], XA[4],XA[5],XA[6],XA[7], bb);
                    bb = *(const uint2*)(wb + SW1F + (2*8+j)*256 + lane*8);
                    MMA4(&acc[j*4], TF[0],TF[1],TF[2],TF[3], bb);
                }
                EPI64(acc, wb + SB1, HA);

                // ---- L2: N=64, K=64
                #pragma unroll
                for (int j = 0; j < 8; j++){
                    uint2 bb = *(const uint2*)(wb + SW2F + (0*8+j)*256 + lane*8);
                    MMA4_INIT(&acc[j*4], HA[0],HA[1],HA[2],HA[3], bb);
                    #pragma unroll
                    for (int ks = 1; ks < 4; ks++){
                        bb = *(const uint2*)(wb + SW2F + (ks*8+j)*256 + lane*8);
                        MMA4(&acc[j*4], HA[ks*4+0],HA[ks*4+1],HA[ks*4+2],HA[ks*4+3], bb);
                    }
                }
                EPI64(acc, wb + SB2, HA);

                // ---- L3: N=32, K=64
                float a3[16];
                #pragma unroll
                for (int j = 0; j < 4; j++){
                    uint2 bb = *(const uint2*)(wb + SW3F + (0*4+j)*256 + lane*8);
                    MMA4_INIT(&a3[j*4], HA[0],HA[1],HA[2],HA[3], bb);
                    #pragma unroll
                    for (int ks = 1; ks < 4; ks++){
                        bb = *(const uint2*)(wb + SW3F + (ks*4+j)*256 + lane*8);
                        MMA4(&a3[j*4], HA[ks*4+0],HA[ks*4+1],HA[ks*4+2],HA[ks*4+3], bb);
                    }
                }
                {
                    const float* b3p = (const float*)(wb + SB3);
                    u32 fr[8];
                    #pragma unroll
                    for (int j = 0; j < 4; j++){
                        float2 bv = *(const float2*)(b3p + j*8 + 2*q);
                        float c0 = a3[j*4+0] + bv.x, c1 = a3[j*4+1] + bv.y;
                        float c2 = a3[j*4+2] + bv.x, c3 = a3[j*4+3] + bv.y;
                        dxs[j*4+0] += c0; dxs[j*4+1] += c1; dxs[j*4+2] += c2; dxs[j*4+3] += c3;
                        fr[j*2+0] = f2h2(c0, c1); fr[j*2+1] = f2h2(c2, c3);
                    }
                    uint4* fp = (uint4*)(smem + SFBASE + warp*8192 + e*1024 + lane*32);
                    fp[0] = make_uint4(fr[0], fr[1], fr[2], fr[3]);
                    fp[1] = make_uint4(fr[4], fr[5], fr[6], fr[7]);
                }
            } // experts

            // ---- gating GEMM1: A = [xin | dx_mean], N=64, K=64
            u32 DXF[8];
            #pragma unroll
            for (int jj = 0; jj < 2; jj++){
                int j0 = jj*2, j1 = jj*2+1;
                DXF[jj*4+0] = f2h2(dxs[j0*4+0]*0.125f, dxs[j0*4+1]*0.125f);
                DXF[jj*4+1] = f2h2(dxs[j0*4+2]*0.125f, dxs[j0*4+3]*0.125f);
                DXF[jj*4+2] = f2h2(dxs[j1*4+0]*0.125f, dxs[j1*4+1]*0.125f);
                DXF[jj*4+3] = f2h2(dxs[j1*4+2]*0.125f, dxs[j1*4+3]*0.125f);
            }
            {
                float acc[32];
                #pragma unroll
                for (int j = 0; j < 8; j++){
                    uint2 bb;
                    bb = *(const uint2*)(smem + SGW1F + (0*8+j)*256 + lane*8);
                    MMA4_INIT(&acc[j*4], XA[0],XA[1],XA[2],XA[3], bb);
                    bb = *(const uint2*)(smem + SGW1F + (1*8+j)*256 + lane*8);
                    MMA4(&acc[j*4], XA[4],XA[5],XA[6],XA[7], bb);
                    bb = *(const uint2*)(smem + SGW1F + (2*8+j)*256 + lane*8);
                    MMA4(&acc[j*4], DXF[0],DXF[1],DXF[2],DXF[3], bb);
                    bb = *(const uint2*)(smem + SGW1F + (3*8+j)*256 + lane*8);
                    MMA4(&acc[j*4], DXF[4],DXF[5],DXF[6],DXF[7], bb);
                }
                EPI64(acc, smem + SGB1, HA);
            }
            // ---- gating GEMM2: N=8 logits + softmax
            float w0, w1, w80, w81;
            {
                float z[4];
                uint2 bb = *(const uint2*)(smem + SGW2F + 0*256 + lane*8);
                MMA4_INIT(z, HA[0],HA[1],HA[2],HA[3], bb);
                #pragma unroll
                for (int ks = 1; ks < 4; ks++){
                    bb = *(const uint2*)(smem + SGW2F + ks*256 + lane*8);
                    MMA4(z, HA[ks*4+0],HA[ks*4+1],HA[ks*4+2],HA[ks*4+3], bb);
                }
                float2 bv = *(const float2*)((const float*)(smem + SGB2) + 2*q);
                z[0] += bv.x; z[1] += bv.y; z[2] += bv.x; z[3] += bv.y;
                float m0 = fmaxf(z[0], z[1]);
                m0 = fmaxf(m0, __shfl_xor_sync(0xffffffffu, m0, 1));
                m0 = fmaxf(m0, __shfl_xor_sync(0xffffffffu, m0, 2));
                float e0 = exp_fast(z[0]-m0), e1 = exp_fast(z[1]-m0);
                float s0 = e0 + e1;
                s0 += __shfl_xor_sync(0xffffffffu, s0, 1);
                s0 += __shfl_xor_sync(0xffffffffu, s0, 2);
                float i0 = rcp_fast(s0);
                w0 = e0*i0; w1 = e1*i0;
                float m1 = fmaxf(z[2], z[3]);
                m1 = fmaxf(m1, __shfl_xor_sync(0xffffffffu, m1, 1));
                m1 = fmaxf(m1, __shfl_xor_sync(0xffffffffu, m1, 2));
                float e2 = exp_fast(z[2]-m1), e3 = exp_fast(z[3]-m1);
                float s1 = e2 + e3;
                s1 += __shfl_xor_sync(0xffffffffu, s1, 1);
                s1 += __shfl_xor_sync(0xffffffffu, s1, 2);
                float i1 = rcp_fast(s1);
                w80 = e2*i1; w81 = e3*i1;
            }
            // exchange expert weights within quad (lane q holds experts 2q,2q+1)
            float wA[8], wB[8];
            #pragma unroll
            for (int qq = 0; qq < 4; qq++){
                int src = (lane & ~3) | qq;
                wA[2*qq+0] = __shfl_sync(0xffffffffu, w0,  src);
                wA[2*qq+1] = __shfl_sync(0xffffffffu, w1,  src);
                wB[2*qq+0] = __shfl_sync(0xffffffffu, w80, src);
                wB[2*qq+1] = __shfl_sync(0xffffffffu, w81, src);
            }
            // combine k = sum_e wgt[e] * f_e (per-lane-private F slots)
            #pragma unroll
            for (int c = 0; c < 16; c++) kk[c] = 0.f;
            #pragma unroll
            for (int e2 = 0; e2 < 8; e2++){
                const uint4* fp = (const uint4*)(smem + SFBASE + warp*8192 + e2*1024 + lane*32);
                uint4 fa = fp[0], fb = fp[1];
                float2 t;
                t = h22f2(fa.x); kk[0] = fmaf(wA[e2], t.x, kk[0]); kk[1] = fmaf(wA[e2], t.y, kk[1]);
                t = h22f2(fa.y); kk[2] = fmaf(wB[e2], t.x, kk[2]); kk[3] = fmaf(wB[e2], t.y, kk[3]);
                t = h22f2(fa.z); kk[4] = fmaf(wA[e2], t.x, kk[4]); kk[5] = fmaf(wA[e2], t.y, kk[5]);
                t = h22f2(fa.w); kk[6] = fmaf(wB[e2], t.x, kk[6]); kk[7] = fmaf(wB[e2], t.y, kk[7]);
                t = h22f2(fb.x); kk[8] = fmaf(wA[e2], t.x, kk[8]); kk[9] = fmaf(wA[e2], t.y, kk[9]);
                t = h22f2(fb.y); kk[10] = fmaf(wB[e2], t.x, kk[10]); kk[11] = fmaf(wB[e2], t.y, kk[11]);
                t = h22f2(fb.z); kk[12] = fmaf(wA[e2], t.x, kk[12]); kk[13] = fmaf(wA[e2], t.y, kk[13]);
                t = h22f2(fb.w); kk[14] = fmaf(wB[e2], t.x, kk[14]); kk[15] = fmaf(wB[e2], t.y, kk[15]);
            }
            const float ws = (sub == 0 || sub == 3) ? 1.f : 2.f;
            #pragma unroll
            for (int c = 0; c < 16; c++) ksum[c] = fmaf(ws, kk[c], ksum[c]);
        } // sub

        const float sc = dt * (1.f/6.f);
        #pragma unroll
        for (int c = 0; c < 16; c++) x[c] = fmaf(sc, ksum[c], x[c]);
        #pragma unroll
        for (int j = 0; j < 4; j++){
            *(float2*)(out + row0*320 + (s+1)*32 + j*8 + 2*q)     = make_float2(x[j*4+0], x[j*4+1]);
            *(float2*)(out + (row0+8)*320 + (s+1)*32 + j*8 + 2*q) = make_float2(x[j*4+2], x[j*4+3]);
        }
    } // step
}

extern "C" void kernel_launch(void* const* d_in, const int* in_sizes, int n_in,
                              void* d_out, int out_size)
{
    (void)in_sizes; (void)n_in; (void)out_size;
    conv_weights<<<128, 256>>>(
        (const float*)d_in[2],  (const float*)d_in[4], (const float*)d_in[6],
        (const float*)d_in[8],  (const float*)d_in[10]);
    cudaFuncSetAttribute(ameode_mma, cudaFuncAttributeMaxDynamicSharedMemorySize, SMEM_BYTES);
    ameode_mma<<<128, CTA, SMEM_BYTES>>>(
        (const float*)d_in[0],  (const float*)d_in[1],
        (const float*)d_in[3],  (const float*)d_in[5], (const float*)d_in[7],
        (const float*)d_in[9],  (const float*)d_in[11],
        (float*)d_out);
}